// round 15
// baseline (speedup 1.0000x reference)
#include <cuda_runtime.h>
#include <cuda_bf16.h>
#include <math.h>

#define T_TOKENS 131072   // 32 * 64 * 64

// ---------------- scratch (device globals, no allocation) ----------------
__device__ float          g_xr [T_TOKENS * 128];   // 64 MB (fp32 residual base)
__device__ __nv_bfloat16  g_ln [T_TOKENS * 128];   // 32 MB (bf16 LN'd activations)
__device__ __nv_bfloat16  g_qkv[T_TOKENS * 384];   // 96 MB ([q|k|v], ch = head*32+e)
__device__ __nv_bfloat16  g_att[T_TOKENS * 128];   // 32 MB
__device__ __nv_bfloat16  g_h  [T_TOKENS * 512];   // 128 MB
__device__ __nv_bfloat16  g_wb [262144];           // bf16 weight pool (512 KB)
__device__ float          g_qb [768];              // permuted qkv biases (wq, sq)

// weight pool offsets
#define W_WQ 0
#define W_WP 49152
#define W_M1 65536
#define W_M2 131072
#define W_SQ 196608
#define W_SP 245760

// ---------------- helpers ----------------
__device__ __forceinline__ void mma_bf16(float c[4], const unsigned a[4], const unsigned b0, const unsigned b1) {
    asm volatile(
        "mma.sync.aligned.m16n8k16.row.col.f32.bf16.bf16.f32 "
        "{%0,%1,%2,%3}, {%4,%5,%6,%7}, {%8,%9}, {%0,%1,%2,%3};\n"
        : "+f"(c[0]), "+f"(c[1]), "+f"(c[2]), "+f"(c[3])
        : "r"(a[0]), "r"(a[1]), "r"(a[2]), "r"(a[3]), "r"(b0), "r"(b1));
}
__device__ __forceinline__ void ldsm4(unsigned r[4], unsigned addr) {
    asm volatile("ldmatrix.sync.aligned.m8n8.x4.shared.b16 {%0,%1,%2,%3}, [%4];"
        : "=r"(r[0]), "=r"(r[1]), "=r"(r[2]), "=r"(r[3]) : "r"(addr));
}
__device__ __forceinline__ void ldsm4t(unsigned r[4], unsigned addr) {
    asm volatile("ldmatrix.sync.aligned.m8n8.x4.trans.shared.b16 {%0,%1,%2,%3}, [%4];"
        : "=r"(r[0]), "=r"(r[1]), "=r"(r[2]), "=r"(r[3]) : "r"(addr));
}
__device__ __forceinline__ float gelu_exact(float x) {
    return 0.5f * x * (1.0f + erff(x * 0.70710678118654752f));
}
__device__ __forceinline__ void cp16b(__nv_bfloat16* dst, const __nv_bfloat16* src) {
    unsigned s = (unsigned)__cvta_generic_to_shared(dst);
    asm volatile("cp.async.cg.shared.global [%0], [%1], 16;\n" :: "r"(s), "l"(src));
}
__device__ __forceinline__ void cp_commit() { asm volatile("cp.async.commit_group;\n"); }
__device__ __forceinline__ void cp_wait_n(int n) {
    if (n == 0)      asm volatile("cp.async.wait_group 0;\n");
    else if (n == 1) asm volatile("cp.async.wait_group 1;\n");
    else             asm volatile("cp.async.wait_group 2;\n");
}
__device__ __forceinline__ void bf8_to_f8(uint4 u, float* f) {
    const __nv_bfloat162* h = (const __nv_bfloat162*)&u;
#pragma unroll
    for (int q = 0; q < 4; ++q) {
        float2 t = __bfloat1622float2(h[q]);
        f[2 * q] = t.x; f[2 * q + 1] = t.y;
    }
}
__device__ __forceinline__ uint4 pack8(const float* f) {
    uint4 u; __nv_bfloat162* p = (__nv_bfloat162*)&u;
#pragma unroll
    for (int j = 0; j < 4; ++j) p[j] = __floats2bfloat162_rn(f[2 * j], f[2 * j + 1]);
    return u;
}

// ---------------- weight pool conversion (fp32 -> bf16) ----------------
__global__ void k_wconv(const float* __restrict__ wq, const float* __restrict__ wp,
                        const float* __restrict__ m1, const float* __restrict__ m2,
                        const float* __restrict__ sq, const float* __restrict__ sp,
                        __nv_bfloat16* __restrict__ out) {
    int idx = (blockIdx.x * blockDim.x + threadIdx.x) * 4;
    const float* src; int base;
    if      (idx < W_WP) { src = wq; base = W_WQ; }
    else if (idx < W_M1) { src = wp; base = W_WP; }
    else if (idx < W_M2) { src = m1; base = W_M1; }
    else if (idx < W_SQ) { src = m2; base = W_M2; }
    else if (idx < W_SP) { src = sq; base = W_SQ; }
    else                 { src = sp; base = W_SP; }
    float4 v = *(const float4*)(src + (idx - base));
    *(__nv_bfloat162*)(out + idx)     = __floats2bfloat162_rn(v.x, v.y);
    *(__nv_bfloat162*)(out + idx + 2) = __floats2bfloat162_rn(v.z, v.w);
}

// permuted QKV weights: new col n' = part*128 + head*32 + e; old = (e*4+head)*3 + part
__global__ void k_wqkv(const float* __restrict__ W, const float* __restrict__ bsrc,
                       __nv_bfloat16* __restrict__ outW, float* __restrict__ outB) {
    int n = blockIdx.x * 256 + threadIdx.x;     // 49152 = 192 blocks * 256
    int kk = n / 384, np = n % 384;
    int part = np >> 7, rch = np & 127, head = rch >> 5, e = rch & 31;
    int nold = (e * 4 + head) * 3 + part;
    outW[kk * 384 + np] = __float2bfloat16(W[kk * 384 + nold]);
    if (n < 384) outB[np] = bsrc[nold];
}

// ---------------- transpose (B,C,HW) -> (B,HW,C) ----------------
__global__ void k_transpose(const float* __restrict__ x, float* __restrict__ xr) {
    __shared__ float tile[32][33];
    int b  = blockIdx.z;
    int s0 = blockIdx.x * 32;
    int c0 = blockIdx.y * 32;
    const float* xb = x + (size_t)b * 128 * 4096;
    int tx = threadIdx.x, ty = threadIdx.y;  // 32 x 8
#pragma unroll
    for (int i = 0; i < 32; i += 8)
        tile[ty + i][tx] = xb[(size_t)(c0 + ty + i) * 4096 + s0 + tx];
    __syncthreads();
    float* xrb = xr + (size_t)b * 4096 * 128;
#pragma unroll
    for (int i = 0; i < 32; i += 8)
        xrb[(size_t)(s0 + ty + i) * 128 + c0 + tx] = tile[tx][ty + i];
}

// ---------------- LN (fp32 in -> bf16 out), one warp per token ----------------
__global__ void k_ln_bf16(const float* __restrict__ in, const float* __restrict__ g,
                          const float* __restrict__ bta, __nv_bfloat16* __restrict__ out) {
    int warp = (blockIdx.x * blockDim.x + threadIdx.x) >> 5;
    int lane = threadIdx.x & 31;
    if (warp >= T_TOKENS) return;
    float4 v = ((const float4*)(in + (size_t)warp * 128))[lane];
    float s = v.x + v.y + v.z + v.w;
#pragma unroll
    for (int o = 16; o; o >>= 1) s += __shfl_xor_sync(0xffffffffu, s, o);
    float mu = s * (1.0f / 128.0f);
    float dx = v.x - mu, dy = v.y - mu, dz = v.z - mu, dw = v.w - mu;
    float q = dx * dx + dy * dy + dz * dz + dw * dw;
#pragma unroll
    for (int o = 16; o; o >>= 1) q += __shfl_xor_sync(0xffffffffu, q, o);
    float rstd = rsqrtf(q * (1.0f / 128.0f) + 1e-5f);
    float4 gv = ((const float4*)g)[lane];
    float4 bv = ((const float4*)bta)[lane];
    uint2 o2;
    ((__nv_bfloat162*)&o2)[0] = __floats2bfloat162_rn(dx * rstd * gv.x + bv.x, dy * rstd * gv.y + bv.y);
    ((__nv_bfloat162*)&o2)[1] = __floats2bfloat162_rn(dz * rstd * gv.z + bv.z, dw * rstd * gv.w + bv.w);
    ((uint2*)(out + (size_t)warp * 128))[lane] = o2;
}

// ---------------- persistent-A multi-N-tile bf16 GEMM (K=128) ----------------
// A(128x128) resident in smem; CTA sweeps NT N-tiles of 128 with a 4-stage B ring.
// N = NT*128. grid = (M/128). smem: A[128][136] + 4 x B[32][136] = 69632 B.
#define MSA 136
#define SB 136
#define MA_OFF (128 * MSA)                   // elems (17408)
#define MBSTG (32 * SB)                      // elems per B stage (4352)
#define GEMM_M_SMEM ((MA_OFF + 4 * MBSTG) * 2)   // 69632 bytes

template <int NT, int ACT, bool RES, bool LNOUT, typename OT>
__global__ __launch_bounds__(256, 2)
void k_gemm_m(const __nv_bfloat16* __restrict__ Ab, const __nv_bfloat16* __restrict__ Bb,
              const float* __restrict__ bias, const float* __restrict__ res,
              OT* __restrict__ C, const float* __restrict__ lng,
              const float* __restrict__ lnb, __nv_bfloat16* __restrict__ lnout,
              int M) {
    extern __shared__ __nv_bfloat16 smem[];
    const unsigned smbase = (unsigned)__cvta_generic_to_shared(smem);
    const int K = 128, N = NT * 128, GT = NT * 4;

    const int tid  = threadIdx.x;
    const int lane = tid & 31;
    const int wid  = tid >> 5;
    const int wm   = (wid >> 1) * 32;
    const int wn   = (wid & 1) * 64;
    const int g    = lane >> 2;
    const int tg   = lane & 3;
    const size_t bm = (size_t)blockIdx.x * 128;

    // A stage mapping: row, 64-col half
    const int ar = tid >> 1, ach = (tid & 1) * 64;
    // B stage mapping: k-row, 16-col chunk
    const int br = tid >> 3, bc = (tid & 7) * 16;

    // ---- prologue: A (one group) + B tiles 0..2 ----
    {
        const __nv_bfloat16* As = Ab + (bm + ar) * (size_t)K + ach;
        __nv_bfloat16* ad = smem + ar * MSA + ach;
#pragma unroll
        for (int i = 0; i < 8; ++i) cp16b(ad + i * 8, As + i * 8);
        cp_commit();
    }
    auto load_b = [&](int gt) {
        const int nt = gt >> 2, kt = gt & 3;
        const __nv_bfloat16* Bs = Bb + (size_t)(kt * 32 + br) * N + nt * 128 + bc;
        __nv_bfloat16* bd = smem + MA_OFF + (gt & 3) * MBSTG + br * SB + bc;
        cp16b(bd,     Bs);
        cp16b(bd + 8, Bs + 8);
        cp_commit();
    };
    load_b(0); load_b(1); load_b(2);

    // ldmatrix per-lane bases
    const int lq = lane & 7, lh = (lane >> 3) & 1, lt = lane >> 4;
    const unsigned aBase = smbase + (unsigned)(((wm + lq + lh * 8) * MSA + lt * 8) * 2);
    const unsigned bBase = smbase + (unsigned)(MA_OFF * 2)
                         + (unsigned)(((lq + lh * 8) * SB + wn + lt * 8) * 2);

#pragma unroll 1
    for (int nt = 0; nt < NT; ++nt) {
        float acc[2][8][4];
#pragma unroll
        for (int i = 0; i < 2; ++i)
#pragma unroll
            for (int j = 0; j < 8; ++j)
#pragma unroll
                for (int r = 0; r < 4; ++r) acc[i][j][r] = 0.f;

#pragma unroll
        for (int kt = 0; kt < 4; ++kt) {
            const int gt = nt * 4 + kt;
            int allow = GT - 1 - gt; if (allow > 2) allow = 2;
            cp_wait_n(allow);
            __syncthreads();
            if (gt + 3 < GT) load_b(gt + 3);

            const unsigned bStg = bBase + (unsigned)((gt & 3) * MBSTG * 2);
#pragma unroll
            for (int ks = 0; ks < 2; ++ks) {
                const unsigned kA = (unsigned)((kt * 32 + ks * 16) * 2);
                const unsigned kB = (unsigned)(ks * 16 * SB * 2);
                unsigned af[2][4];
                ldsm4(af[0], aBase + kA);
                ldsm4(af[1], aBase + kA + (unsigned)(16 * MSA * 2));
                unsigned bfr[4][4];
#pragma unroll
                for (int p = 0; p < 4; ++p)
                    ldsm4t(bfr[p], bStg + kB + (unsigned)(p * 16 * 2));
#pragma unroll
                for (int mi = 0; mi < 2; ++mi)
#pragma unroll
                    for (int p = 0; p < 4; ++p) {
                        mma_bf16(acc[mi][2 * p],     af[mi], bfr[p][0], bfr[p][1]);
                        mma_bf16(acc[mi][2 * p + 1], af[mi], bfr[p][2], bfr[p][3]);
                    }
            }
        }

        // ---- epilogue for this N-tile ----
        const int bn = nt * 128;
        float rs[4] = {0.f, 0.f, 0.f, 0.f};
        float rq[4] = {0.f, 0.f, 0.f, 0.f};
#pragma unroll
        for (int mi = 0; mi < 2; ++mi) {
            const size_t r0 = bm + wm + mi * 16 + g;
#pragma unroll
            for (int ni = 0; ni < 8; ++ni) {
                const size_t c0 = bn + wn + ni * 8 + 2 * tg;
                const float bx = bias[c0], by = bias[c0 + 1];
                float v0 = acc[mi][ni][0] + bx, v1 = acc[mi][ni][1] + by;
                float v2 = acc[mi][ni][2] + bx, v3 = acc[mi][ni][3] + by;
                if (ACT == 1) {
                    v0 = gelu_exact(v0); v1 = gelu_exact(v1);
                    v2 = gelu_exact(v2); v3 = gelu_exact(v3);
                }
                const size_t o0 = r0 * N + c0;
                const size_t o1 = (r0 + 8) * N + c0;
                if (RES) {
                    float2 ra = *(const float2*)(res + o0);
                    float2 rb = *(const float2*)(res + o1);
                    v0 += ra.x; v1 += ra.y; v2 += rb.x; v3 += rb.y;
                }
                if (LNOUT) {
                    rs[mi * 2 + 0] += v0 + v1;
                    rq[mi * 2 + 0] += v0 * v0 + v1 * v1;
                    rs[mi * 2 + 1] += v2 + v3;
                    rq[mi * 2 + 1] += v2 * v2 + v3 * v3;
                    acc[mi][ni][0] = v0; acc[mi][ni][1] = v1;
                    acc[mi][ni][2] = v2; acc[mi][ni][3] = v3;
                }
                if (sizeof(OT) == 2) {
                    __nv_bfloat162* Cb = (__nv_bfloat162*)C;
                    Cb[o0 >> 1] = __floats2bfloat162_rn(v0, v1);
                    Cb[o1 >> 1] = __floats2bfloat162_rn(v2, v3);
                } else {
                    float2 w0; w0.x = v0; w0.y = v1;
                    float2 w1; w1.x = v2; w1.y = v3;
                    *(float2*)((float*)C + o0) = w0;
                    *(float2*)((float*)C + o1) = w1;
                }
            }
        }

        if (LNOUT) {   // only instantiated with NT==1 (N==128)
#pragma unroll
            for (int slot = 0; slot < 4; ++slot) {
#pragma unroll
                for (int o = 1; o < 4; o <<= 1) {
                    rs[slot] += __shfl_xor_sync(0xffffffffu, rs[slot], o);
                    rq[slot] += __shfl_xor_sync(0xffffffffu, rq[slot], o);
                }
            }
            __syncthreads();
            float2* sstP = (float2*)smem;
            float2* sstF = sstP + 256;
            if (tg == 0) {
#pragma unroll
                for (int slot = 0; slot < 4; ++slot) {
                    int r = wm + (slot >> 1) * 16 + g + (slot & 1) * 8;
                    float2 p; p.x = rs[slot]; p.y = rq[slot];
                    sstP[r * 2 + (wid & 1)] = p;
                }
            }
            __syncthreads();
            if (tid < 128) {
                float2 a = sstP[tid * 2], b = sstP[tid * 2 + 1];
                float s = a.x + b.x, q = a.y + b.y;
                float mu = s * (1.0f / 128.0f);
                float var = q * (1.0f / 128.0f) - mu * mu;
                float2 o2; o2.x = mu; o2.y = rsqrtf(var + 1e-5f);
                sstF[tid] = o2;
            }
            __syncthreads();
#pragma unroll
            for (int mi = 0; mi < 2; ++mi) {
                const int ra = wm + mi * 16 + g;
                const float2 sa = sstF[ra];
                const float2 sb = sstF[ra + 8];
#pragma unroll
                for (int ni = 0; ni < 8; ++ni) {
                    const int c = wn + ni * 8 + 2 * tg;
                    const float gx = lng[c], gy = lng[c + 1];
                    const float bx2 = lnb[c], by2 = lnb[c + 1];
                    float l0 = (acc[mi][ni][0] - sa.x) * sa.y * gx + bx2;
                    float l1 = (acc[mi][ni][1] - sa.x) * sa.y * gy + by2;
                    float l2 = (acc[mi][ni][2] - sb.x) * sb.y * gx + bx2;
                    float l3 = (acc[mi][ni][3] - sb.x) * sb.y * gy + by2;
                    __nv_bfloat162* L = (__nv_bfloat162*)lnout;
                    L[((bm + ra) * 128 + c) >> 1]     = __floats2bfloat162_rn(l0, l1);
                    L[((bm + ra + 8) * 128 + c) >> 1] = __floats2bfloat162_rn(l2, l3);
                }
            }
        }
    }
}

// ---------------- bf16 GEMM, 4-stage cp.async ring pipeline (K=512 path) ----------------
#define SA 40
#define ASTG 5120
#define BSTG 4352
#define A_REGION (4 * ASTG)
#define GEMM_SMEM ((A_REGION + 4 * BSTG) * 2)   // 75776 bytes

template <int ACT, bool RES, bool LNOUT, typename OT>
__global__ __launch_bounds__(256, 2)
void k_gemm_b(const __nv_bfloat16* __restrict__ Ab, const __nv_bfloat16* __restrict__ Bb,
              const float* __restrict__ bias, const float* __restrict__ res,
              OT* __restrict__ C, const float* __restrict__ lng,
              const float* __restrict__ lnb, __nv_bfloat16* __restrict__ lnout,
              int M, int N, int K) {
    extern __shared__ __nv_bfloat16 smem[];
    const unsigned smbase = (unsigned)__cvta_generic_to_shared(smem);

    const int tid  = threadIdx.x;
    const int lane = tid & 31;
    const int wid  = tid >> 5;
    const int wm   = (wid >> 1) * 32;
    const int wn   = (wid & 1) * 64;
    const int g    = lane >> 2;
    const int tg   = lane & 3;
    const size_t bm = (size_t)blockIdx.x * 128;
    const size_t bn = (size_t)blockIdx.y * 128;

    const int ar = tid & 127;
    const int ah = (tid >> 7) * 16;
    const int br = tid >> 3;
    const int bc = (tid & 7) * 16;

    const __nv_bfloat16* Agr = Ab + (bm + ar) * (size_t)K + ah;
    const __nv_bfloat16* Bgr = Bb + (size_t)br * N + bn + bc;

    const int lq = lane & 7, lh = (lane >> 3) & 1, lt = lane >> 4;
    const unsigned aRC = (unsigned)(((wm + lq + lh * 8) * SA + lt * 8) * 2);
    const unsigned bRC = (unsigned)(A_REGION * 2) + (unsigned)(((lq + lh * 8) * SB + wn + lt * 8) * 2);

    float acc[2][8][4];
#pragma unroll
    for (int i = 0; i < 2; ++i)
#pragma unroll
        for (int j = 0; j < 8; ++j)
#pragma unroll
            for (int r = 0; r < 4; ++r) acc[i][j][r] = 0.f;

    const int KT = K >> 5;

    auto load_tile = [&](int kt, int stage) {
        const __nv_bfloat16* An = Agr + kt * 32;
        __nv_bfloat16* ad = smem + stage * ASTG + ar * SA + ah;
        cp16b(ad,     An);
        cp16b(ad + 8, An + 8);
        const __nv_bfloat16* Bn = Bgr + (size_t)(kt * 32) * N;
        __nv_bfloat16* bd = smem + A_REGION + stage * BSTG + br * SB + bc;
        cp16b(bd,     Bn);
        cp16b(bd + 8, Bn + 8);
        cp_commit();
    };

    const int PRE = KT < 3 ? KT : 3;
    for (int t = 0; t < PRE; ++t) load_tile(t, t);

    for (int kt = 0; kt < KT; ++kt) {
        int allow = KT - 1 - kt; if (allow > 2) allow = 2;
        cp_wait_n(allow);
        __syncthreads();
        if (kt + 3 < KT) load_tile(kt + 3, (kt + 3) & 3);

        const int stg = kt & 3;
        const unsigned aBase = smbase + (unsigned)(stg * ASTG * 2) + aRC;
        const unsigned bBase = smbase + (unsigned)(stg * BSTG * 2) + bRC;
#pragma unroll
        for (int ks = 0; ks < 2; ++ks) {
            const unsigned kA = (unsigned)(ks * 16 * 2);
            const unsigned kB = (unsigned)(ks * 16 * SB * 2);
            unsigned af[2][4];
            ldsm4(af[0], aBase + kA);
            ldsm4(af[1], aBase + kA + (unsigned)(16 * SA * 2));
            unsigned bfr[4][4];
#pragma unroll
            for (int p = 0; p < 4; ++p)
                ldsm4t(bfr[p], bBase + kB + (unsigned)(p * 16 * 2));
#pragma unroll
            for (int mi = 0; mi < 2; ++mi)
#pragma unroll
                for (int p = 0; p < 4; ++p) {
                    mma_bf16(acc[mi][2 * p],     af[mi], bfr[p][0], bfr[p][1]);
                    mma_bf16(acc[mi][2 * p + 1], af[mi], bfr[p][2], bfr[p][3]);
                }
        }
    }

    // ---- epilogue ----
    float rs[4] = {0.f, 0.f, 0.f, 0.f};
    float rq[4] = {0.f, 0.f, 0.f, 0.f};
#pragma unroll
    for (int mi = 0; mi < 2; ++mi) {
        const size_t r0 = bm + wm + mi * 16 + g;
#pragma unroll
        for (int ni = 0; ni < 8; ++ni) {
            const size_t c0 = bn + wn + ni * 8 + 2 * tg;
            const float bx = bias[c0], by = bias[c0 + 1];
            float v0 = acc[mi][ni][0] + bx, v1 = acc[mi][ni][1] + by;
            float v2 = acc[mi][ni][2] + bx, v3 = acc[mi][ni][3] + by;
            if (ACT == 1) {
                v0 = gelu_exact(v0); v1 = gelu_exact(v1);
                v2 = gelu_exact(v2); v3 = gelu_exact(v3);
            }
            const size_t o0 = r0 * N + c0;
            const size_t o1 = (r0 + 8) * N + c0;
            if (RES) {
                float2 ra = *(const float2*)(res + o0);
                float2 rb = *(const float2*)(res + o1);
                v0 += ra.x; v1 += ra.y; v2 += rb.x; v3 += rb.y;
            }
            if (LNOUT) {
                rs[mi * 2 + 0] += v0 + v1;
                rq[mi * 2 + 0] += v0 * v0 + v1 * v1;
                rs[mi * 2 + 1] += v2 + v3;
                rq[mi * 2 + 1] += v2 * v2 + v3 * v3;
                acc[mi][ni][0] = v0; acc[mi][ni][1] = v1;
                acc[mi][ni][2] = v2; acc[mi][ni][3] = v3;
            }
            if (sizeof(OT) == 2) {
                __nv_bfloat162* Cb = (__nv_bfloat162*)C;
                Cb[o0 >> 1] = __floats2bfloat162_rn(v0, v1);
                Cb[o1 >> 1] = __floats2bfloat162_rn(v2, v3);
            } else {
                float2 w0; w0.x = v0; w0.y = v1;
                float2 w1; w1.x = v2; w1.y = v3;
                *(float2*)((float*)C + o0) = w0;
                *(float2*)((float*)C + o1) = w1;
            }
        }
    }

    if (LNOUT) {
#pragma unroll
        for (int slot = 0; slot < 4; ++slot) {
#pragma unroll
            for (int o = 1; o < 4; o <<= 1) {
                rs[slot] += __shfl_xor_sync(0xffffffffu, rs[slot], o);
                rq[slot] += __shfl_xor_sync(0xffffffffu, rq[slot], o);
            }
        }
        __syncthreads();
        float2* sstP = (float2*)smem;
        float2* sstF = sstP + 256;
        if (tg == 0) {
#pragma unroll
            for (int slot = 0; slot < 4; ++slot) {
                int r = wm + (slot >> 1) * 16 + g + (slot & 1) * 8;
                float2 p; p.x = rs[slot]; p.y = rq[slot];
                sstP[r * 2 + (wid & 1)] = p;
            }
        }
        __syncthreads();
        if (tid < 128) {
            float2 a = sstP[tid * 2], b = sstP[tid * 2 + 1];
            float s = a.x + b.x, q = a.y + b.y;
            float mu = s * (1.0f / 128.0f);
            float var = q * (1.0f / 128.0f) - mu * mu;
            float2 o2; o2.x = mu; o2.y = rsqrtf(var + 1e-5f);
            sstF[tid] = o2;
        }
        __syncthreads();
#pragma unroll
        for (int mi = 0; mi < 2; ++mi) {
            const int ra = wm + mi * 16 + g;
            const float2 sa = sstF[ra];
            const float2 sb = sstF[ra + 8];
#pragma unroll
            for (int ni = 0; ni < 8; ++ni) {
                const int c = wn + ni * 8 + 2 * tg;
                const float gx = lng[c], gy = lng[c + 1];
                const float bx2 = lnb[c], by2 = lnb[c + 1];
                float l0 = (acc[mi][ni][0] - sa.x) * sa.y * gx + bx2;
                float l1 = (acc[mi][ni][1] - sa.x) * sa.y * gy + by2;
                float l2 = (acc[mi][ni][2] - sb.x) * sb.y * gx + bx2;
                float l3 = (acc[mi][ni][3] - sb.x) * sb.y * gy + by2;
                __nv_bfloat162* L = (__nv_bfloat162*)lnout;
                L[((bm + ra) * 128 + c) >> 1]     = __floats2bfloat162_rn(l0, l1);
                L[((bm + ra + 8) * 128 + c) >> 1] = __floats2bfloat162_rn(l2, l3);
            }
        }
    }
}

// ---------------- window attention v2: strip-based, zero shfl ----------------
#define AIN 392
#define AOUT 136
#define ATT_SMEM ((128 * AIN + 128 * AOUT) * 2)   // 135168 bytes

__global__ __launch_bounds__(256)
void k_attn2(const __nv_bfloat16* __restrict__ qkv, const float* __restrict__ pos,
             __nv_bfloat16* __restrict__ att, int shifted) {
    extern __shared__ __nv_bfloat16 sm2[];
    __nv_bfloat16* sin  = sm2;                 // [128][392]
    __nv_bfloat16* sout = sm2 + 128 * AIN;     // [128][136]
    __shared__ float spos[9];
    const int tid = threadIdx.x;
    const int b = blockIdx.x >> 5, s = blockIdx.x & 31;
    if (tid < 9) spos[tid] = pos[tid];

    {
        const int tok  = tid >> 1;
        const int half = tid & 1;
        const int r    = tok >> 6;
        const int c    = tok & 63;
        const int gr   = shifted ? ((2 * s + 1 + r) & 63) : (2 * s + r);
        const int gc   = shifted ? ((c + 1) & 63) : c;
        const __nv_bfloat16* src = qkv + ((size_t)b * 4096 + gr * 64 + gc) * 384 + half * 192;
        __nv_bfloat16* dst = sin + tok * AIN + half * 192;
#pragma unroll
        for (int i = 0; i < 24; ++i)
            ((uint4*)dst)[i] = ((const uint4*)src)[i];
    }
    __syncthreads();

    const int win  = tid >> 3;
    const int head = (tid >> 1) & 3;
    const int ih   = tid & 1;
    const int qch  = head * 32;
    const int t0 = ih * 64 + win * 2;
    const int t1 = t0 + 1;
    int tk[4];
#pragma unroll
    for (int j = 0; j < 4; ++j) tk[j] = (j >> 1) * 64 + win * 2 + (j & 1);

    float d[2][4] = {{0.f, 0.f, 0.f, 0.f}, {0.f, 0.f, 0.f, 0.f}};
#pragma unroll
    for (int c = 0; c < 4; ++c) {
        float qa[8], qb[8];
        bf8_to_f8(*(const uint4*)&sin[t0 * AIN + qch + c * 8], qa);
        bf8_to_f8(*(const uint4*)&sin[t1 * AIN + qch + c * 8], qb);
#pragma unroll
        for (int j = 0; j < 4; ++j) {
            float kf[8];
            bf8_to_f8(*(const uint4*)&sin[tk[j] * AIN + 128 + qch + c * 8], kf);
#pragma unroll
            for (int ch = 0; ch < 8; ++ch) {
                d[0][j] += qa[ch] * kf[ch];
                d[1][j] += qb[ch] * kf[ch];
            }
        }
    }

    const float scale = 0.17677669529663687f;
    float p[2][4];
#pragma unroll
    for (int i2 = 0; i2 < 2; ++i2) {
        float w[4];
#pragma unroll
        for (int j = 0; j < 4; ++j) {
            int dx = (j >> 1) - ih + 1;
            int dy = (j & 1) - i2 + 1;
            float v = d[i2][j] * scale + spos[dx * 3 + dy];
            if (shifted) {
                if (s == 31 && ((j >> 1) != ih)) v = -1e30f;
                if (win == 31 && ((j & 1) != i2)) v = -1e30f;
            }
            w[j] = v;
        }
        float m = fmaxf(fmaxf(w[0], w[1]), fmaxf(w[2], w[3]));
        float e0 = __expf(w[0] - m), e1 = __expf(w[1] - m);
        float e2 = __expf(w[2] - m), e3 = __expf(w[3] - m);
        float inv = 1.0f / (e0 + e1 + e2 + e3);
        p[i2][0] = e0 * inv; p[i2][1] = e1 * inv;
        p[i2][2] = e2 * inv; p[i2][3] = e3 * inv;
    }

#pragma unroll
    for (int c = 0; c < 4; ++c) {
        float o0[8] = {0,0,0,0,0,0,0,0}, o1[8] = {0,0,0,0,0,0,0,0};
#pragma unroll
        for (int j = 0; j < 4; ++j) {
            float vf[8];
            bf8_to_f8(*(const uint4*)&sin[tk[j] * AIN + 256 + qch + c * 8], vf);
#pragma unroll
            for (int ch = 0; ch < 8; ++ch) {
                o0[ch] += p[0][j] * vf[ch];
                o1[ch] += p[1][j] * vf[ch];
            }
        }
        *(uint4*)&sout[t0 * AOUT + qch + c * 8] = pack8(o0);
        *(uint4*)&sout[t1 * AOUT + qch + c * 8] = pack8(o1);
    }
    __syncthreads();

    const size_t gbase = ((size_t)b * 4096 + (size_t)(2 * s) * 64) * 128;
#pragma unroll
    for (int q = 0; q < 8; ++q) {
        int idx = q * 256 + tid;
        int tok = idx >> 4, c8 = idx & 15;
        *(uint4*)(att + gbase + (size_t)tok * 128 + c8 * 8) =
            *(const uint4*)&sout[tok * AOUT + c8 * 8];
    }
}

// ---------------- host orchestration ----------------
extern "C" void kernel_launch(void* const* d_in, const int* in_sizes, int n_in,
                              void* d_out, int out_size) {
    const float* x    = (const float*)d_in[0];
    const float* ln_g = (const float*)d_in[1];
    const float* ln_b = (const float*)d_in[2];
    const float* wq_W = (const float*)d_in[3];
    const float* wq_b = (const float*)d_in[4];
    const float* wp_W = (const float*)d_in[5];
    const float* wp_b = (const float*)d_in[6];
    const float* wpos = (const float*)d_in[7];
    const float* sq_W = (const float*)d_in[8];
    const float* sq_b = (const float*)d_in[9];
    const float* sp_W = (const float*)d_in[10];
    const float* sp_b = (const float*)d_in[11];
    const float* spos = (const float*)d_in[12];
    const float* m1_W = (const float*)d_in[13];
    const float* m1_b = (const float*)d_in[14];
    const float* m2_W = (const float*)d_in[15];
    const float* m2_b = (const float*)d_in[16];
    float* y = (float*)d_out;

    float *p_xr, *p_qb;
    __nv_bfloat16 *p_ln, *p_qkv, *p_att, *p_h, *p_wb;
    cudaGetSymbolAddress((void**)&p_xr,  g_xr);
    cudaGetSymbolAddress((void**)&p_ln,  g_ln);
    cudaGetSymbolAddress((void**)&p_qkv, g_qkv);
    cudaGetSymbolAddress((void**)&p_att, g_att);
    cudaGetSymbolAddress((void**)&p_h,   g_h);
    cudaGetSymbolAddress((void**)&p_wb,  g_wb);
    cudaGetSymbolAddress((void**)&p_qb,  g_qb);

    static bool s_attr = false;
    if (!s_attr) {
        cudaFuncSetAttribute(k_gemm_m<3, 0, false, false, __nv_bfloat16>,
                             cudaFuncAttributeMaxDynamicSharedMemorySize, GEMM_M_SMEM);
        cudaFuncSetAttribute(k_gemm_m<1, 0, true, true, float>,
                             cudaFuncAttributeMaxDynamicSharedMemorySize, GEMM_M_SMEM);
        cudaFuncSetAttribute(k_gemm_m<4, 1, false, false, __nv_bfloat16>,
                             cudaFuncAttributeMaxDynamicSharedMemorySize, GEMM_M_SMEM);
        cudaFuncSetAttribute(k_gemm_b<0, true, true, float>,
                             cudaFuncAttributeMaxDynamicSharedMemorySize, GEMM_SMEM);
        cudaFuncSetAttribute(k_gemm_b<0, true, false, float>,
                             cudaFuncAttributeMaxDynamicSharedMemorySize, GEMM_SMEM);
        cudaFuncSetAttribute(k_attn2,
                             cudaFuncAttributeMaxDynamicSharedMemorySize, ATT_SMEM);
        s_attr = true;
    }

    const int M = T_TOKENS;
    dim3 tgrid(128, 4, 32), tblk(32, 8);

    k_wconv<<<256, 256>>>(wq_W, wp_W, m1_W, m2_W, sq_W, sp_W, p_wb);
    k_wqkv<<<192, 256>>>(wq_W, wq_b, p_wb + W_WQ, p_qb);
    k_wqkv<<<192, 256>>>(sq_W, sq_b, p_wb + W_SQ, p_qb + 384);
    k_transpose<<<tgrid, tblk>>>(x, p_xr);
    k_ln_bf16<<<T_TOKENS / 8, 256>>>(p_xr, ln_g, ln_b, p_ln);

    // ---- block 1: W-MSA ----
    k_gemm_m<3, 0, false, false, __nv_bfloat16><<<M / 128, 256, GEMM_M_SMEM>>>(
        p_ln, p_wb + W_WQ, p_qb, nullptr, p_qkv, nullptr, nullptr, nullptr, M);
    k_attn2<<<1024, 256, ATT_SMEM>>>(p_qkv, wpos, p_att, 0);
    k_gemm_m<1, 0, true, true, float><<<M / 128, 256, GEMM_M_SMEM>>>(
        p_att, p_wb + W_WP, wp_b, p_xr, y, ln_g, ln_b, p_ln, M);
    // MLP
    k_gemm_m<4, 1, false, false, __nv_bfloat16><<<M / 128, 256, GEMM_M_SMEM>>>(
        p_ln, p_wb + W_M1, m1_b, nullptr, p_h, nullptr, nullptr, nullptr, M);
    k_gemm_b<0, true, true, float><<<dim3(M / 128, 1), 256, GEMM_SMEM>>>(
        p_h, p_wb + W_M2, m2_b, y, y, ln_g, ln_b, p_ln, M, 128, 512);

    // ---- block 2: SW-MSA ----
    k_gemm_m<3, 0, false, false, __nv_bfloat16><<<M / 128, 256, GEMM_M_SMEM>>>(
        p_ln, p_wb + W_SQ, p_qb + 384, nullptr, p_qkv, nullptr, nullptr, nullptr, M);
    k_attn2<<<1024, 256, ATT_SMEM>>>(p_qkv, spos, p_att, 1);
    k_gemm_m<1, 0, true, true, float><<<M / 128, 256, GEMM_M_SMEM>>>(
        p_att, p_wb + W_SP, sp_b, y, y, ln_g, ln_b, p_ln, M);
    // MLP (final)
    k_gemm_m<4, 1, false, false, __nv_bfloat16><<<M / 128, 256, GEMM_M_SMEM>>>(
        p_ln, p_wb + W_M1, m1_b, nullptr, p_h, nullptr, nullptr, nullptr, M);
    k_gemm_b<0, true, false, float><<<dim3(M / 128, 1), 256, GEMM_SMEM>>>(
        p_h, p_wb + W_M2, m2_b, y, y, nullptr, nullptr, nullptr, M, 128, 512);
}

// round 16
// speedup vs baseline: 1.4199x; 1.4199x over previous
#include <cuda_runtime.h>
#include <cuda_bf16.h>
#include <math.h>

#define T_TOKENS 131072   // 32 * 64 * 64

// ---------------- scratch (device globals, no allocation) ----------------
__device__ float          g_xr [T_TOKENS * 128];   // 64 MB (fp32 residual base)
__device__ __nv_bfloat16  g_ln [T_TOKENS * 128];   // 32 MB (bf16 LN'd activations)
__device__ __nv_bfloat16  g_qkv[T_TOKENS * 384];   // 96 MB ([q|k|v], ch = head*32+e)
__device__ __nv_bfloat16  g_att[T_TOKENS * 128];   // 32 MB
__device__ __nv_bfloat16  g_h  [T_TOKENS * 512];   // 128 MB
__device__ __nv_bfloat16  g_wb [262144];           // bf16 weight pool (512 KB)
__device__ float          g_qb [768];              // permuted qkv biases (wq, sq)

// weight pool offsets
#define W_WQ 0
#define W_WP 49152
#define W_M1 65536
#define W_M2 131072
#define W_SQ 196608
#define W_SP 245760

// ---------------- helpers ----------------
__device__ __forceinline__ void mma_bf16(float c[4], const unsigned a[4], const unsigned b0, const unsigned b1) {
    asm volatile(
        "mma.sync.aligned.m16n8k16.row.col.f32.bf16.bf16.f32 "
        "{%0,%1,%2,%3}, {%4,%5,%6,%7}, {%8,%9}, {%0,%1,%2,%3};\n"
        : "+f"(c[0]), "+f"(c[1]), "+f"(c[2]), "+f"(c[3])
        : "r"(a[0]), "r"(a[1]), "r"(a[2]), "r"(a[3]), "r"(b0), "r"(b1));
}
__device__ __forceinline__ void ldsm4(unsigned r[4], unsigned addr) {
    asm volatile("ldmatrix.sync.aligned.m8n8.x4.shared.b16 {%0,%1,%2,%3}, [%4];"
        : "=r"(r[0]), "=r"(r[1]), "=r"(r[2]), "=r"(r[3]) : "r"(addr));
}
__device__ __forceinline__ void ldsm4t(unsigned r[4], unsigned addr) {
    asm volatile("ldmatrix.sync.aligned.m8n8.x4.trans.shared.b16 {%0,%1,%2,%3}, [%4];"
        : "=r"(r[0]), "=r"(r[1]), "=r"(r[2]), "=r"(r[3]) : "r"(addr));
}
__device__ __forceinline__ float gelu_exact(float x) {
    return 0.5f * x * (1.0f + erff(x * 0.70710678118654752f));
}
__device__ __forceinline__ void cp16b(__nv_bfloat16* dst, const __nv_bfloat16* src) {
    unsigned s = (unsigned)__cvta_generic_to_shared(dst);
    asm volatile("cp.async.cg.shared.global [%0], [%1], 16;\n" :: "r"(s), "l"(src));
}
__device__ __forceinline__ void cp_commit() { asm volatile("cp.async.commit_group;\n"); }
__device__ __forceinline__ void cp_wait_n(int n) {
    if (n == 0)      asm volatile("cp.async.wait_group 0;\n");
    else if (n == 1) asm volatile("cp.async.wait_group 1;\n");
    else             asm volatile("cp.async.wait_group 2;\n");
}
__device__ __forceinline__ void bf8_to_f8(uint4 u, float* f) {
    const __nv_bfloat162* h = (const __nv_bfloat162*)&u;
#pragma unroll
    for (int q = 0; q < 4; ++q) {
        float2 t = __bfloat1622float2(h[q]);
        f[2 * q] = t.x; f[2 * q + 1] = t.y;
    }
}
__device__ __forceinline__ uint4 pack8(const float* f) {
    uint4 u; __nv_bfloat162* p = (__nv_bfloat162*)&u;
#pragma unroll
    for (int j = 0; j < 4; ++j) p[j] = __floats2bfloat162_rn(f[2 * j], f[2 * j + 1]);
    return u;
}

// ---------------- weight pool conversion (fp32 -> bf16) ----------------
__global__ void k_wconv(const float* __restrict__ wq, const float* __restrict__ wp,
                        const float* __restrict__ m1, const float* __restrict__ m2,
                        const float* __restrict__ sq, const float* __restrict__ sp,
                        __nv_bfloat16* __restrict__ out) {
    int idx = (blockIdx.x * blockDim.x + threadIdx.x) * 4;
    const float* src; int base;
    if      (idx < W_WP) { src = wq; base = W_WQ; }
    else if (idx < W_M1) { src = wp; base = W_WP; }
    else if (idx < W_M2) { src = m1; base = W_M1; }
    else if (idx < W_SQ) { src = m2; base = W_M2; }
    else if (idx < W_SP) { src = sq; base = W_SQ; }
    else                 { src = sp; base = W_SP; }
    float4 v = *(const float4*)(src + (idx - base));
    *(__nv_bfloat162*)(out + idx)     = __floats2bfloat162_rn(v.x, v.y);
    *(__nv_bfloat162*)(out + idx + 2) = __floats2bfloat162_rn(v.z, v.w);
}

// permuted QKV weights: new col n' = part*128 + head*32 + e; old = (e*4+head)*3 + part
__global__ void k_wqkv(const float* __restrict__ W, const float* __restrict__ bsrc,
                       __nv_bfloat16* __restrict__ outW, float* __restrict__ outB) {
    int n = blockIdx.x * 256 + threadIdx.x;     // 49152 = 192 blocks * 256
    int kk = n / 384, np = n % 384;
    int part = np >> 7, rch = np & 127, head = rch >> 5, e = rch & 31;
    int nold = (e * 4 + head) * 3 + part;
    outW[kk * 384 + np] = __float2bfloat16(W[kk * 384 + nold]);
    if (n < 384) outB[np] = bsrc[nold];
}

// ---------------- fused transpose + LN: (B,C,HW) -> xr fp32 (B,HW,C) + ln bf16 ----------------
// One block per (batch, 32-token strip). 256 threads. Reads x once.
__global__ __launch_bounds__(256)
void k_trln(const float* __restrict__ x, const float* __restrict__ g,
            const float* __restrict__ bta, float* __restrict__ xr,
            __nv_bfloat16* __restrict__ ln) {
    __shared__ float tile[128][33];
    const int b  = blockIdx.y;
    const int s0 = blockIdx.x * 32;
    const int tx = threadIdx.x & 31, ty = threadIdx.x >> 5;   // 32 x 8
    const float* xb = x + (size_t)b * 128 * 4096;
#pragma unroll
    for (int i = 0; i < 16; ++i)
        tile[ty + i * 8][tx] = xb[(size_t)(ty + i * 8) * 4096 + s0 + tx];
    __syncthreads();

    const int lane = tx;
    float4 gv = ((const float4*)g)[lane];
    float4 bv = ((const float4*)bta)[lane];
#pragma unroll
    for (int j = 0; j < 4; ++j) {
        const int t = ty * 4 + j;                 // token within strip (0..31)
        float4 v;
        v.x = tile[lane * 4 + 0][t];
        v.y = tile[lane * 4 + 1][t];
        v.z = tile[lane * 4 + 2][t];
        v.w = tile[lane * 4 + 3][t];
        const size_t tok = (size_t)b * 4096 + s0 + t;
        ((float4*)(xr + tok * 128))[lane] = v;    // fp32 residual base
        float s = v.x + v.y + v.z + v.w;
#pragma unroll
        for (int o = 16; o; o >>= 1) s += __shfl_xor_sync(0xffffffffu, s, o);
        float mu = s * (1.0f / 128.0f);
        float dx = v.x - mu, dy = v.y - mu, dz = v.z - mu, dw = v.w - mu;
        float q = dx * dx + dy * dy + dz * dz + dw * dw;
#pragma unroll
        for (int o = 16; o; o >>= 1) q += __shfl_xor_sync(0xffffffffu, q, o);
        float rstd = rsqrtf(q * (1.0f / 128.0f) + 1e-5f);
        uint2 o2;
        ((__nv_bfloat162*)&o2)[0] = __floats2bfloat162_rn(dx * rstd * gv.x + bv.x, dy * rstd * gv.y + bv.y);
        ((__nv_bfloat162*)&o2)[1] = __floats2bfloat162_rn(dz * rstd * gv.z + bv.z, dw * rstd * gv.w + bv.w);
        ((uint2*)(ln + tok * 128))[lane] = o2;
    }
}

// ---------------- bf16 GEMM, 4-stage cp.async ring pipeline ----------------
#define SA 40
#define SB 136
#define ASTG 5120
#define BSTG 4352
#define A_REGION (4 * ASTG)
#define GEMM_SMEM ((A_REGION + 4 * BSTG) * 2)   // 75776 bytes

template <int ACT, bool RES, bool LNOUT, typename OT>
__global__ __launch_bounds__(256, 2)
void k_gemm_b(const __nv_bfloat16* __restrict__ Ab, const __nv_bfloat16* __restrict__ Bb,
              const float* __restrict__ bias, const float* __restrict__ res,
              OT* __restrict__ C, const float* __restrict__ lng,
              const float* __restrict__ lnb, __nv_bfloat16* __restrict__ lnout,
              int M, int N, int K) {
    extern __shared__ __nv_bfloat16 smem[];
    const unsigned smbase = (unsigned)__cvta_generic_to_shared(smem);

    const int tid  = threadIdx.x;
    const int lane = tid & 31;
    const int wid  = tid >> 5;
    const int wm   = (wid >> 1) * 32;
    const int wn   = (wid & 1) * 64;
    const int g    = lane >> 2;
    const int tg   = lane & 3;
    const size_t bm = (size_t)blockIdx.x * 128;
    const size_t bn = (size_t)blockIdx.y * 128;

    const int ar = tid & 127;
    const int ah = (tid >> 7) * 16;
    const int br = tid >> 3;
    const int bc = (tid & 7) * 16;

    const __nv_bfloat16* Agr = Ab + (bm + ar) * (size_t)K + ah;
    const __nv_bfloat16* Bgr = Bb + (size_t)br * N + bn + bc;

    const int lq = lane & 7, lh = (lane >> 3) & 1, lt = lane >> 4;
    const unsigned aRC = (unsigned)(((wm + lq + lh * 8) * SA + lt * 8) * 2);
    const unsigned bRC = (unsigned)(A_REGION * 2) + (unsigned)(((lq + lh * 8) * SB + wn + lt * 8) * 2);

    float acc[2][8][4];
#pragma unroll
    for (int i = 0; i < 2; ++i)
#pragma unroll
        for (int j = 0; j < 8; ++j)
#pragma unroll
            for (int r = 0; r < 4; ++r) acc[i][j][r] = 0.f;

    const int KT = K >> 5;

    auto load_tile = [&](int kt, int stage) {
        const __nv_bfloat16* An = Agr + kt * 32;
        __nv_bfloat16* ad = smem + stage * ASTG + ar * SA + ah;
        cp16b(ad,     An);
        cp16b(ad + 8, An + 8);
        const __nv_bfloat16* Bn = Bgr + (size_t)(kt * 32) * N;
        __nv_bfloat16* bd = smem + A_REGION + stage * BSTG + br * SB + bc;
        cp16b(bd,     Bn);
        cp16b(bd + 8, Bn + 8);
        cp_commit();
    };

    const int PRE = KT < 3 ? KT : 3;
    for (int t = 0; t < PRE; ++t) load_tile(t, t);

    for (int kt = 0; kt < KT; ++kt) {
        int allow = KT - 1 - kt; if (allow > 2) allow = 2;
        cp_wait_n(allow);
        __syncthreads();
        if (kt + 3 < KT) load_tile(kt + 3, (kt + 3) & 3);

        const int stg = kt & 3;
        const unsigned aBase = smbase + (unsigned)(stg * ASTG * 2) + aRC;
        const unsigned bBase = smbase + (unsigned)(stg * BSTG * 2) + bRC;
#pragma unroll
        for (int ks = 0; ks < 2; ++ks) {
            const unsigned kA = (unsigned)(ks * 16 * 2);
            const unsigned kB = (unsigned)(ks * 16 * SB * 2);
            unsigned af[2][4];
            ldsm4(af[0], aBase + kA);
            ldsm4(af[1], aBase + kA + (unsigned)(16 * SA * 2));
            unsigned bfr[4][4];
#pragma unroll
            for (int p = 0; p < 4; ++p)
                ldsm4t(bfr[p], bBase + kB + (unsigned)(p * 16 * 2));
#pragma unroll
            for (int mi = 0; mi < 2; ++mi)
#pragma unroll
                for (int p = 0; p < 4; ++p) {
                    mma_bf16(acc[mi][2 * p],     af[mi], bfr[p][0], bfr[p][1]);
                    mma_bf16(acc[mi][2 * p + 1], af[mi], bfr[p][2], bfr[p][3]);
                }
        }
    }

    // ---- epilogue ----
    float rs[4] = {0.f, 0.f, 0.f, 0.f};
    float rq[4] = {0.f, 0.f, 0.f, 0.f};
#pragma unroll
    for (int mi = 0; mi < 2; ++mi) {
        const size_t r0 = bm + wm + mi * 16 + g;
#pragma unroll
        for (int ni = 0; ni < 8; ++ni) {
            const size_t c0 = bn + wn + ni * 8 + 2 * tg;
            const float bx = bias[c0], by = bias[c0 + 1];
            float v0 = acc[mi][ni][0] + bx, v1 = acc[mi][ni][1] + by;
            float v2 = acc[mi][ni][2] + bx, v3 = acc[mi][ni][3] + by;
            if (ACT == 1) {
                v0 = gelu_exact(v0); v1 = gelu_exact(v1);
                v2 = gelu_exact(v2); v3 = gelu_exact(v3);
            }
            const size_t o0 = r0 * N + c0;
            const size_t o1 = (r0 + 8) * N + c0;
            if (RES) {
                float2 ra = *(const float2*)(res + o0);
                float2 rb = *(const float2*)(res + o1);
                v0 += ra.x; v1 += ra.y; v2 += rb.x; v3 += rb.y;
            }
            if (LNOUT) {
                rs[mi * 2 + 0] += v0 + v1;
                rq[mi * 2 + 0] += v0 * v0 + v1 * v1;
                rs[mi * 2 + 1] += v2 + v3;
                rq[mi * 2 + 1] += v2 * v2 + v3 * v3;
                acc[mi][ni][0] = v0; acc[mi][ni][1] = v1;
                acc[mi][ni][2] = v2; acc[mi][ni][3] = v3;
            }
            if (sizeof(OT) == 2) {
                __nv_bfloat162* Cb = (__nv_bfloat162*)C;
                Cb[o0 >> 1] = __floats2bfloat162_rn(v0, v1);
                Cb[o1 >> 1] = __floats2bfloat162_rn(v2, v3);
            } else {
                float2 w0; w0.x = v0; w0.y = v1;
                float2 w1; w1.x = v2; w1.y = v3;
                *(float2*)((float*)C + o0) = w0;
                *(float2*)((float*)C + o1) = w1;
            }
        }
    }

    if (LNOUT) {
#pragma unroll
        for (int slot = 0; slot < 4; ++slot) {
#pragma unroll
            for (int o = 1; o < 4; o <<= 1) {
                rs[slot] += __shfl_xor_sync(0xffffffffu, rs[slot], o);
                rq[slot] += __shfl_xor_sync(0xffffffffu, rq[slot], o);
            }
        }
        __syncthreads();
        float2* sstP = (float2*)smem;
        float2* sstF = sstP + 256;
        if (tg == 0) {
#pragma unroll
            for (int slot = 0; slot < 4; ++slot) {
                int r = wm + (slot >> 1) * 16 + g + (slot & 1) * 8;
                float2 p; p.x = rs[slot]; p.y = rq[slot];
                sstP[r * 2 + (wid & 1)] = p;
            }
        }
        __syncthreads();
        if (tid < 128) {
            float2 a = sstP[tid * 2], b = sstP[tid * 2 + 1];
            float s = a.x + b.x, q = a.y + b.y;
            float mu = s * (1.0f / 128.0f);
            float var = q * (1.0f / 128.0f) - mu * mu;
            float2 o2; o2.x = mu; o2.y = rsqrtf(var + 1e-5f);
            sstF[tid] = o2;
        }
        __syncthreads();
#pragma unroll
        for (int mi = 0; mi < 2; ++mi) {
            const int ra = wm + mi * 16 + g;
            const float2 sa = sstF[ra];
            const float2 sb = sstF[ra + 8];
#pragma unroll
            for (int ni = 0; ni < 8; ++ni) {
                const int c = wn + ni * 8 + 2 * tg;
                const float gx = lng[c], gy = lng[c + 1];
                const float bx2 = lnb[c], by2 = lnb[c + 1];
                float l0 = (acc[mi][ni][0] - sa.x) * sa.y * gx + bx2;
                float l1 = (acc[mi][ni][1] - sa.x) * sa.y * gy + by2;
                float l2 = (acc[mi][ni][2] - sb.x) * sb.y * gx + bx2;
                float l3 = (acc[mi][ni][3] - sb.x) * sb.y * gy + by2;
                __nv_bfloat162* L = (__nv_bfloat162*)lnout;
                L[((bm + ra) * 128 + c) >> 1]     = __floats2bfloat162_rn(l0, l1);
                L[((bm + ra + 8) * 128 + c) >> 1] = __floats2bfloat162_rn(l2, l3);
            }
        }
    }
}

// ---------------- window attention v2: strip-based, zero shfl ----------------
#define AIN 392
#define AOUT 136
#define ATT_SMEM ((128 * AIN + 128 * AOUT) * 2)   // 135168 bytes

__global__ __launch_bounds__(256)
void k_attn2(const __nv_bfloat16* __restrict__ qkv, const float* __restrict__ pos,
             __nv_bfloat16* __restrict__ att, int shifted) {
    extern __shared__ __nv_bfloat16 sm2[];
    __nv_bfloat16* sin  = sm2;                 // [128][392]
    __nv_bfloat16* sout = sm2 + 128 * AIN;     // [128][136]
    __shared__ float spos[9];
    const int tid = threadIdx.x;
    const int b = blockIdx.x >> 5, s = blockIdx.x & 31;
    if (tid < 9) spos[tid] = pos[tid];

    {
        const int tok  = tid >> 1;
        const int half = tid & 1;
        const int r    = tok >> 6;
        const int c    = tok & 63;
        const int gr   = shifted ? ((2 * s + 1 + r) & 63) : (2 * s + r);
        const int gc   = shifted ? ((c + 1) & 63) : c;
        const __nv_bfloat16* src = qkv + ((size_t)b * 4096 + gr * 64 + gc) * 384 + half * 192;
        __nv_bfloat16* dst = sin + tok * AIN + half * 192;
#pragma unroll
        for (int i = 0; i < 24; ++i)
            ((uint4*)dst)[i] = ((const uint4*)src)[i];
    }
    __syncthreads();

    const int win  = tid >> 3;
    const int head = (tid >> 1) & 3;
    const int ih   = tid & 1;
    const int qch  = head * 32;
    const int t0 = ih * 64 + win * 2;
    const int t1 = t0 + 1;
    int tk[4];
#pragma unroll
    for (int j = 0; j < 4; ++j) tk[j] = (j >> 1) * 64 + win * 2 + (j & 1);

    float d[2][4] = {{0.f, 0.f, 0.f, 0.f}, {0.f, 0.f, 0.f, 0.f}};
#pragma unroll
    for (int c = 0; c < 4; ++c) {
        float qa[8], qb[8];
        bf8_to_f8(*(const uint4*)&sin[t0 * AIN + qch + c * 8], qa);
        bf8_to_f8(*(const uint4*)&sin[t1 * AIN + qch + c * 8], qb);
#pragma unroll
        for (int j = 0; j < 4; ++j) {
            float kf[8];
            bf8_to_f8(*(const uint4*)&sin[tk[j] * AIN + 128 + qch + c * 8], kf);
#pragma unroll
            for (int ch = 0; ch < 8; ++ch) {
                d[0][j] += qa[ch] * kf[ch];
                d[1][j] += qb[ch] * kf[ch];
            }
        }
    }

    const float scale = 0.17677669529663687f;
    float p[2][4];
#pragma unroll
    for (int i2 = 0; i2 < 2; ++i2) {
        float w[4];
#pragma unroll
        for (int j = 0; j < 4; ++j) {
            int dx = (j >> 1) - ih + 1;
            int dy = (j & 1) - i2 + 1;
            float v = d[i2][j] * scale + spos[dx * 3 + dy];
            if (shifted) {
                if (s == 31 && ((j >> 1) != ih)) v = -1e30f;
                if (win == 31 && ((j & 1) != i2)) v = -1e30f;
            }
            w[j] = v;
        }
        float m = fmaxf(fmaxf(w[0], w[1]), fmaxf(w[2], w[3]));
        float e0 = __expf(w[0] - m), e1 = __expf(w[1] - m);
        float e2 = __expf(w[2] - m), e3 = __expf(w[3] - m);
        float inv = 1.0f / (e0 + e1 + e2 + e3);
        p[i2][0] = e0 * inv; p[i2][1] = e1 * inv;
        p[i2][2] = e2 * inv; p[i2][3] = e3 * inv;
    }

#pragma unroll
    for (int c = 0; c < 4; ++c) {
        float o0[8] = {0,0,0,0,0,0,0,0}, o1[8] = {0,0,0,0,0,0,0,0};
#pragma unroll
        for (int j = 0; j < 4; ++j) {
            float vf[8];
            bf8_to_f8(*(const uint4*)&sin[tk[j] * AIN + 256 + qch + c * 8], vf);
#pragma unroll
            for (int ch = 0; ch < 8; ++ch) {
                o0[ch] += p[0][j] * vf[ch];
                o1[ch] += p[1][j] * vf[ch];
            }
        }
        *(uint4*)&sout[t0 * AOUT + qch + c * 8] = pack8(o0);
        *(uint4*)&sout[t1 * AOUT + qch + c * 8] = pack8(o1);
    }
    __syncthreads();

    const size_t gbase = ((size_t)b * 4096 + (size_t)(2 * s) * 64) * 128;
#pragma unroll
    for (int q = 0; q < 8; ++q) {
        int idx = q * 256 + tid;
        int tok = idx >> 4, c8 = idx & 15;
        *(uint4*)(att + gbase + (size_t)tok * 128 + c8 * 8) =
            *(const uint4*)&sout[tok * AOUT + c8 * 8];
    }
}

// ---------------- host orchestration ----------------
extern "C" void kernel_launch(void* const* d_in, const int* in_sizes, int n_in,
                              void* d_out, int out_size) {
    const float* x    = (const float*)d_in[0];
    const float* ln_g = (const float*)d_in[1];
    const float* ln_b = (const float*)d_in[2];
    const float* wq_W = (const float*)d_in[3];
    const float* wq_b = (const float*)d_in[4];
    const float* wp_W = (const float*)d_in[5];
    const float* wp_b = (const float*)d_in[6];
    const float* wpos = (const float*)d_in[7];
    const float* sq_W = (const float*)d_in[8];
    const float* sq_b = (const float*)d_in[9];
    const float* sp_W = (const float*)d_in[10];
    const float* sp_b = (const float*)d_in[11];
    const float* spos = (const float*)d_in[12];
    const float* m1_W = (const float*)d_in[13];
    const float* m1_b = (const float*)d_in[14];
    const float* m2_W = (const float*)d_in[15];
    const float* m2_b = (const float*)d_in[16];
    float* y = (float*)d_out;

    float *p_xr, *p_qb;
    __nv_bfloat16 *p_ln, *p_qkv, *p_att, *p_h, *p_wb;
    cudaGetSymbolAddress((void**)&p_xr,  g_xr);
    cudaGetSymbolAddress((void**)&p_ln,  g_ln);
    cudaGetSymbolAddress((void**)&p_qkv, g_qkv);
    cudaGetSymbolAddress((void**)&p_att, g_att);
    cudaGetSymbolAddress((void**)&p_h,   g_h);
    cudaGetSymbolAddress((void**)&p_wb,  g_wb);
    cudaGetSymbolAddress((void**)&p_qb,  g_qb);

    static bool s_attr = false;
    if (!s_attr) {
        cudaFuncSetAttribute(k_gemm_b<0, false, false, __nv_bfloat16>,
                             cudaFuncAttributeMaxDynamicSharedMemorySize, GEMM_SMEM);
        cudaFuncSetAttribute(k_gemm_b<0, true, true, float>,
                             cudaFuncAttributeMaxDynamicSharedMemorySize, GEMM_SMEM);
        cudaFuncSetAttribute(k_gemm_b<1, false, false, __nv_bfloat16>,
                             cudaFuncAttributeMaxDynamicSharedMemorySize, GEMM_SMEM);
        cudaFuncSetAttribute(k_gemm_b<0, true, false, float>,
                             cudaFuncAttributeMaxDynamicSharedMemorySize, GEMM_SMEM);
        cudaFuncSetAttribute(k_attn2,
                             cudaFuncAttributeMaxDynamicSharedMemorySize, ATT_SMEM);
        s_attr = true;
    }

    const int M = T_TOKENS;

    k_wconv<<<256, 256>>>(wq_W, wp_W, m1_W, m2_W, sq_W, sp_W, p_wb);
    k_wqkv<<<192, 256>>>(wq_W, wq_b, p_wb + W_WQ, p_qb);
    k_wqkv<<<192, 256>>>(sq_W, sq_b, p_wb + W_SQ, p_qb + 384);
    k_trln<<<dim3(128, 32), 256>>>(x, ln_g, ln_b, p_xr, p_ln);

    // ---- block 1: W-MSA ----
    k_gemm_b<0, false, false, __nv_bfloat16><<<dim3(M / 128, 3), 256, GEMM_SMEM>>>(
        p_ln, p_wb + W_WQ, p_qb, nullptr, p_qkv, nullptr, nullptr, nullptr, M, 384, 128);
    k_attn2<<<1024, 256, ATT_SMEM>>>(p_qkv, wpos, p_att, 0);
    k_gemm_b<0, true, true, float><<<dim3(M / 128, 1), 256, GEMM_SMEM>>>(
        p_att, p_wb + W_WP, wp_b, p_xr, y, ln_g, ln_b, p_ln, M, 128, 128);
    // MLP
    k_gemm_b<1, false, false, __nv_bfloat16><<<dim3(M / 128, 4), 256, GEMM_SMEM>>>(
        p_ln, p_wb + W_M1, m1_b, nullptr, p_h, nullptr, nullptr, nullptr, M, 512, 128);
    k_gemm_b<0, true, true, float><<<dim3(M / 128, 1), 256, GEMM_SMEM>>>(
        p_h, p_wb + W_M2, m2_b, y, y, ln_g, ln_b, p_ln, M, 128, 512);

    // ---- block 2: SW-MSA ----
    k_gemm_b<0, false, false, __nv_bfloat16><<<dim3(M / 128, 3), 256, GEMM_SMEM>>>(
        p_ln, p_wb + W_SQ, p_qb + 384, nullptr, p_qkv, nullptr, nullptr, nullptr, M, 384, 128);
    k_attn2<<<1024, 256, ATT_SMEM>>>(p_qkv, spos, p_att, 1);
    k_gemm_b<0, true, true, float><<<dim3(M / 128, 1), 256, GEMM_SMEM>>>(
        p_att, p_wb + W_SP, sp_b, y, y, ln_g, ln_b, p_ln, M, 128, 128);
    // MLP (final)
    k_gemm_b<1, false, false, __nv_bfloat16><<<dim3(M / 128, 4), 256, GEMM_SMEM>>>(
        p_ln, p_wb + W_M1, m1_b, nullptr, p_h, nullptr, nullptr, nullptr, M, 512, 128);
    k_gemm_b<0, true, false, float><<<dim3(M / 128, 1), 256, GEMM_SMEM>>>(
        p_h, p_wb + W_M2, m2_b, y, y, nullptr, nullptr, nullptr, M, 128, 512);
}